// round 6
// baseline (speedup 1.0000x reference)
#include <cuda_runtime.h>
#include <cuda_bf16.h>
#include <math.h>

// Problem constants
#define BB 4
#define SS 2048
#define EE 256
#define HH 8
#define DK 32
#define MM (BB * SS)
#define KK EE
#define NN EE

#define QT 128            // query tile rows per block
#define JT 64             // key tile cols per iteration
#define NQT (SS / QT)     // 16 query tiles

// Scratch (device globals; no allocation allowed)
__device__ float g_qh[BB * HH * SS * DK];   // [B,H,S,DK]
__device__ float g_kh[BB * HH * SS * DK];
__device__ float g_vh[BB * HH * SS * DK];
__device__ float g_ao[BB * SS * EE];        // attention output [B,S,H*DK]
// score spill: per (bh,qt) block region; total = 32 * 272 * 8192 floats = 285MB
#define SC_BH_STRIDE 2228224
__device__ float g_sc[(size_t)32 * SC_BH_STRIDE];

// ---------------------------------------------------------------------------
// f32x2 packed helpers (Blackwell FFMA2)
// ---------------------------------------------------------------------------
__device__ __forceinline__ unsigned long long ffma2(unsigned long long a,
                                                    unsigned long long b,
                                                    unsigned long long c)
{
    unsigned long long d;
    asm("fma.rn.f32x2 %0, %1, %2, %3;" : "=l"(d) : "l"(a), "l"(b), "l"(c));
    return d;
}
__device__ __forceinline__ float2 u2f(unsigned long long v)
{
    float2 r;
    asm("mov.b64 {%0, %1}, %2;" : "=f"(r.x), "=f"(r.y) : "l"(v));
    return r;
}
__device__ __forceinline__ unsigned long long pack2(float x)
{
    unsigned long long d;
    asm("mov.b64 %0, {%1, %1};" : "=l"(d) : "f"(x));
    return d;
}
__device__ __forceinline__ unsigned long long mul2(unsigned long long a,
                                                   unsigned long long b)
{
    unsigned long long d;
    asm("mul.rn.f32x2 %0, %1, %2;" : "=l"(d) : "l"(a), "l"(b));
    return d;
}

// 16-lane (tx-group) reductions: lanes with same ty are contiguous half-warps
__device__ __forceinline__ float redmax16(float v)
{
#pragma unroll
    for (int off = 8; off > 0; off >>= 1)
        v = fmaxf(v, __shfl_xor_sync(0xffffffffu, v, off, 32));
    return v;
}
__device__ __forceinline__ float redsum16(float v)
{
#pragma unroll
    for (int off = 8; off > 0; off >>= 1)
        v += __shfl_xor_sync(0xffffffffu, v, off, 32);
    return v;
}

// ---------------------------------------------------------------------------
// GEMM: C[M,N] = X[M,K] @ W[N,K]^T + bias[N], 64x64 tile, K-tile 32, FFMA2
// ---------------------------------------------------------------------------
__global__ void gemm_bias_kernel(const float* __restrict__ X,
                                 const float* __restrict__ W,
                                 const float* __restrict__ bias,
                                 float* __restrict__ out,
                                 int permute)
{
    __shared__ float Xs[64][36];
    __shared__ float Ws[64][36];

    const int tid = threadIdx.x;
    const int tx = tid & 15;
    const int ty = tid >> 4;
    const int m0 = blockIdx.x * 64;
    const int n0 = blockIdx.y * 64;

    unsigned long long acc2[4][4];
#pragma unroll
    for (int y = 0; y < 4; y++)
#pragma unroll
        for (int x = 0; x < 4; x++) acc2[y][x] = 0ULL;

    for (int t = 0; t < KK / 32; t++) {
        const int k0 = t * 32;
        __syncthreads();
#pragma unroll
        for (int l = 0; l < 2; l++) {
            int idx = tid + l * 256;
            int r = idx >> 3;
            int c4 = (idx & 7) * 4;
            *(float4*)&Xs[r][c4] = *(const float4*)&X[(size_t)(m0 + r) * KK + k0 + c4];
            *(float4*)&Ws[r][c4] = *(const float4*)&W[(size_t)(n0 + r) * KK + k0 + c4];
        }
        __syncthreads();

#pragma unroll
        for (int kb = 0; kb < 8; kb++) {
            ulonglong2 bv[4];
#pragma unroll
            for (int x = 0; x < 4; x++)
                bv[x] = *(const ulonglong2*)&Ws[tx * 4 + x][kb * 4];
#pragma unroll
            for (int y = 0; y < 4; y++) {
                ulonglong2 av = *(const ulonglong2*)&Xs[ty * 4 + y][kb * 4];
#pragma unroll
                for (int x = 0; x < 4; x++) {
                    acc2[y][x] = ffma2(av.x, bv[x].x, acc2[y][x]);
                    acc2[y][x] = ffma2(av.y, bv[x].y, acc2[y][x]);
                }
            }
        }
    }

#pragma unroll
    for (int y = 0; y < 4; y++) {
#pragma unroll
        for (int x = 0; x < 4; x++) {
            int m = m0 + ty * 4 + y;
            int n = n0 + tx * 4 + x;
            float2 f = u2f(acc2[y][x]);
            float val = f.x + f.y + bias[n];
            if (permute) {
                int b_ = m >> 11;
                int s_ = m & 2047;
                int h_ = n >> 5;
                int d_ = n & 31;
                out[(((size_t)b_ * HH + h_) * SS + s_) * DK + d_] = val;
            } else {
                out[(size_t)m * NN + n] = val;
            }
        }
    }
}

// ---------------------------------------------------------------------------
// Tiled attention with distance-decay.
// Block: 128 query rows of one (b,h). tx=tid&15 (4 cols / 2 out dims),
// ty=tid>>4 (8 rows). Row r0+y's 16 partials live in one 16-lane group.
// ---------------------------------------------------------------------------
struct AttnSmem {
    float Qs[128][36];    // [r][k]  natural row-major
    float Ks[64][36];     // [c][k]  natural row-major
    float Vst[32][68];    // [d][c]  value tile, transposed (c-pairs contiguous)
    float ps[128][68];    // p2 tile
};

__global__ __launch_bounds__(256, 2)
void attn_tile_kernel(const float* __restrict__ qh,
                      const float* __restrict__ kh,
                      const float* __restrict__ vh,
                      const float* __restrict__ gammas,
                      float* gsc,
                      float* __restrict__ ao)
{
    extern __shared__ char smem_raw[];
    AttnSmem* S = (AttnSmem*)smem_raw;

    const int tid = threadIdx.x;
    const int tx = tid & 15;
    const int ty = tid >> 4;
    const int r0 = ty * 8;
    const int c0 = tx * 4;

    // heavy q-tiles launch first
    const int qt = (NQT - 1) - (blockIdx.x >> 5);
    const int bh = blockIdx.x & 31;
    const int h = bh & (HH - 1);
    const int b = bh >> 3;
    const int i0 = qt * QT;
    const int jtiles = 2 * qt + 2;

    const float* qbase = qh + (size_t)bh * SS * DK;
    const float* kbase = kh + (size_t)bh * SS * DK;
    const float* vbase = vh + (size_t)bh * SS * DK;
    float* scbase = gsc + (size_t)bh * SC_BH_STRIDE + (size_t)(qt * qt + qt) * 8192;

    const float g = gammas[h];
    const float gamma = -log1pf(__expf(g));
    const float scale = 0.17677669529663687f;  // 1/sqrt(32)

    // ---- load Q tile (natural layout) ----
#pragma unroll
    for (int l = 0; l < 4; l++) {
        int idx = tid + l * 256;
        int r = idx >> 3;
        int kq = (idx & 7) * 4;
        *(float4*)&S->Qs[r][kq] = *(const float4*)(qbase + (size_t)(i0 + r) * DK + kq);
    }

    float rm1[8], rs1[8];
#pragma unroll
    for (int y = 0; y < 8; y++) { rm1[y] = -3.0e38f; rs1[y] = 0.f; }

    float scr[8][4];

    // =================== PASS 1: scores -> spill + softmax-1 stats ========
    for (int jt = 0; jt < jtiles; jt++) {
        const int j0 = jt * JT;
        __syncthreads();
#pragma unroll
        for (int l = 0; l < 2; l++) {
            int idx = tid + l * 256;
            int c = idx >> 3;
            int kq = (idx & 7) * 4;
            *(float4*)&S->Ks[c][kq] = *(const float4*)(kbase + (size_t)(j0 + c) * DK + kq);
        }
        __syncthreads();

        // QK GEMM with even/odd-k packed partials, x in two halves
#pragma unroll
        for (int xh = 0; xh < 2; xh++) {
            unsigned long long s2r[8][2];
#pragma unroll
            for (int y = 0; y < 8; y++) { s2r[y][0] = 0ULL; s2r[y][1] = 0ULL; }
#pragma unroll
            for (int kb = 0; kb < 8; kb++) {
                ulonglong2 b0 = *(const ulonglong2*)&S->Ks[c0 + 2 * xh][kb * 4];
                ulonglong2 b1 = *(const ulonglong2*)&S->Ks[c0 + 2 * xh + 1][kb * 4];
#pragma unroll
                for (int y = 0; y < 8; y++) {
                    ulonglong2 av = *(const ulonglong2*)&S->Qs[r0 + y][kb * 4];
                    s2r[y][0] = ffma2(av.x, b0.x, s2r[y][0]);
                    s2r[y][0] = ffma2(av.y, b0.y, s2r[y][0]);
                    s2r[y][1] = ffma2(av.x, b1.x, s2r[y][1]);
                    s2r[y][1] = ffma2(av.y, b1.y, s2r[y][1]);
                }
            }
#pragma unroll
            for (int y = 0; y < 8; y++) {
                float2 f0 = u2f(s2r[y][0]);
                float2 f1 = u2f(s2r[y][1]);
                scr[y][2 * xh] = (f0.x + f0.y) * scale;
                scr[y][2 * xh + 1] = (f1.x + f1.y) * scale;
            }
        }

        // causal mask + spill + online stats
        const bool need_mask = (j0 + JT - 1 > i0);
#pragma unroll
        for (int y = 0; y < 8; y++) {
            const int i = i0 + r0 + y;
            if (need_mask) {
#pragma unroll
                for (int x = 0; x < 4; x++)
                    if (j0 + c0 + x > i) scr[y][x] = -1e30f;
            }
            *(float4*)(scbase + (size_t)jt * 8192 + (r0 + y) * 64 + c0) =
                make_float4(scr[y][0], scr[y][1], scr[y][2], scr[y][3]);

            float lm = fmaxf(fmaxf(scr[y][0], scr[y][1]), fmaxf(scr[y][2], scr[y][3]));
            float tm = redmax16(lm);
            float nm = fmaxf(rm1[y], tm);
            float f = __expf(rm1[y] - nm);
            rm1[y] = nm;
            float pe = __expf(scr[y][0] - nm) + __expf(scr[y][1] - nm) +
                       __expf(scr[y][2] - nm) + __expf(scr[y][3] - nm);
            rs1[y] = rs1[y] * f + redsum16(pe);
        }
    }

    float ri1[8];
#pragma unroll
    for (int y = 0; y < 8; y++) ri1[y] = 1.f / rs1[y];

    float rm2[8], rl2[8], rcarry[8];
    unsigned long long acc2[8][2];
#pragma unroll
    for (int y = 0; y < 8; y++) {
        rm2[y] = -3.0e38f; rl2[y] = 0.f; rcarry[y] = 0.f;
        acc2[y][0] = 0ULL; acc2[y][1] = 0ULL;
    }

    // =================== PASS 2: decay + softmax-2 + PV ===================
    for (int jt = 0; jt < jtiles; jt++) {
        const int j0 = jt * JT;
        __syncthreads();   // prev PV done reading Vst / ps

        // reload this thread's spilled scores (same thread wrote them)
        float4 s4[8];
#pragma unroll
        for (int y = 0; y < 8; y++)
            s4[y] = *(const float4*)(scbase + (size_t)jt * 8192 + (r0 + y) * 64 + c0);

        // stage V tile transposed [d][c]
#pragma unroll
        for (int l = 0; l < 2; l++) {
            int idx = tid + l * 256;
            int c = idx >> 3;
            int kq = (idx & 7) * 4;
            float4 vv = *(const float4*)(vbase + (size_t)(j0 + c) * DK + kq);
            S->Vst[kq + 0][c] = vv.x;
            S->Vst[kq + 1][c] = vv.y;
            S->Vst[kq + 2][c] = vv.z;
            S->Vst[kq + 3][c] = vv.w;
        }
        __syncthreads();

#pragma unroll
        for (int y = 0; y < 8; y++) {
            const int i = i0 + r0 + y;
            const float m1 = rm1[y], is1 = ri1[y];
            float sc0 = s4[y].x, sc1 = s4[y].y, sc2 = s4[y].z, sc3 = s4[y].w;

            // normalized s1 + in-thread inclusive prefix
            float e0 = __expf(sc0 - m1) * is1;
            float e1 = __expf(sc1 - m1) * is1;
            float e2 = __expf(sc2 - m1) * is1;
            float e3 = __expf(sc3 - m1) * is1;
            float q1 = e0, q2 = q1 + e1, q3 = q2 + e2, tt = q3 + e3;

            // prefix scan across tx (16 lanes)
            float run = tt;
#pragma unroll
            for (int off = 1; off < 16; off <<= 1) {
                float v = __shfl_up_sync(0xffffffffu, run, off, 16);
                if (tx >= off) run += v;
            }
            float base = rcarry[y] + (run - tt);
            rcarry[y] += __shfl_sync(0xffffffffu, run, 15, 16);

            // distance-decay rescale
            float cums[4] = {base + q1, base + q2, base + q3, base + tt};
            float s2v[4] = {sc0, sc1, sc2, sc3};
#pragma unroll
            for (int x = 0; x < 4; x++) {
                int j = j0 + c0 + x;
                float rem = 1.f - cums[x];
                float posn = fabsf((float)(i - j));
                float dist = sqrtf(fmaxf(rem * posn, 0.f));
                float eff = fmaxf(__expf(dist * gamma), 1e-5f);  // exp<=1: no upper clip
                s2v[x] *= eff;
            }

            // online softmax-2
            float lm = fmaxf(fmaxf(s2v[0], s2v[1]), fmaxf(s2v[2], s2v[3]));
            float tm = redmax16(lm);
            float nm = fmaxf(rm2[y], tm);
            float f = __expf(rm2[y] - nm);
            rm2[y] = nm;
            float p0 = __expf(s2v[0] - nm);
            float p1 = __expf(s2v[1] - nm);
            float p2 = __expf(s2v[2] - nm);
            float p3 = __expf(s2v[3] - nm);
            rl2[y] = rl2[y] * f + redsum16(p0 + p1 + p2 + p3);

            unsigned long long pf = pack2(f);
            acc2[y][0] = mul2(acc2[y][0], pf);
            acc2[y][1] = mul2(acc2[y][1], pf);

            *(float4*)&S->ps[r0 + y][c0] = make_float4(p0, p1, p2, p3);
        }
        __syncwarp();   // ps rows are produced/consumed within the same warp

        // PV with even/odd-c packed partials
        const int d0 = 2 * tx;
#pragma unroll 4
        for (int cb = 0; cb < 16; cb++) {
            ulonglong2 v0 = *(const ulonglong2*)&S->Vst[d0][cb * 4];
            ulonglong2 v1 = *(const ulonglong2*)&S->Vst[d0 + 1][cb * 4];
#pragma unroll
            for (int y = 0; y < 8; y++) {
                ulonglong2 pp = *(const ulonglong2*)&S->ps[r0 + y][cb * 4];
                acc2[y][0] = ffma2(pp.x, v0.x, acc2[y][0]);
                acc2[y][0] = ffma2(pp.y, v0.y, acc2[y][0]);
                acc2[y][1] = ffma2(pp.x, v1.x, acc2[y][1]);
                acc2[y][1] = ffma2(pp.y, v1.y, acc2[y][1]);
            }
        }
    }

    // ---- write output ----
#pragma unroll
    for (int y = 0; y < 8; y++) {
        int i = i0 + r0 + y;
        float inv = 1.f / rl2[y];
        float2 a0 = u2f(acc2[y][0]);
        float2 a1 = u2f(acc2[y][1]);
        size_t base = ((size_t)b * SS + i) * EE + h * DK + 2 * tx;
        ao[base] = (a0.x + a0.y) * inv;
        ao[base + 1] = (a1.x + a1.y) * inv;
    }
}

// ---------------------------------------------------------------------------
extern "C" void kernel_launch(void* const* d_in, const int* in_sizes, int n_in,
                              void* d_out, int out_size)
{
    const float* q      = (const float*)d_in[0];
    const float* k      = (const float*)d_in[1];
    const float* v      = (const float*)d_in[2];
    // d_in[3] = mask (unused; causal structure known)
    const float* Wq     = (const float*)d_in[4];
    const float* bq     = (const float*)d_in[5];
    const float* Wk     = (const float*)d_in[6];
    const float* bk     = (const float*)d_in[7];
    const float* Wv     = (const float*)d_in[8];
    const float* bv     = (const float*)d_in[9];
    const float* Wo     = (const float*)d_in[10];
    const float* bo     = (const float*)d_in[11];
    const float* gammas = (const float*)d_in[12];
    float* out = (float*)d_out;

    float *qh, *kh, *vh, *ao, *sc;
    cudaGetSymbolAddress((void**)&qh, g_qh);
    cudaGetSymbolAddress((void**)&kh, g_kh);
    cudaGetSymbolAddress((void**)&vh, g_vh);
    cudaGetSymbolAddress((void**)&ao, g_ao);
    cudaGetSymbolAddress((void**)&sc, g_sc);

    static bool attr_set = false;
    if (!attr_set) {
        cudaFuncSetAttribute(attn_tile_kernel,
                             cudaFuncAttributeMaxDynamicSharedMemorySize,
                             (int)sizeof(AttnSmem));
        attr_set = true;
    }

    dim3 gblk(256);
    dim3 ggrid(MM / 64, NN / 64);

    gemm_bias_kernel<<<ggrid, gblk>>>(q, Wq, bq, qh, 1);
    gemm_bias_kernel<<<ggrid, gblk>>>(k, Wk, bk, kh, 1);
    gemm_bias_kernel<<<ggrid, gblk>>>(v, Wv, bv, vh, 1);

    attn_tile_kernel<<<BB * HH * NQT, 256, sizeof(AttnSmem)>>>(qh, kh, vh, gammas, sc, ao);

    gemm_bias_kernel<<<ggrid, gblk>>>(ao, Wo, bo, out, 0);
}

// round 9
// speedup vs baseline: 1.1385x; 1.1385x over previous
#include <cuda_runtime.h>
#include <cuda_bf16.h>
#include <math.h>

// Problem constants
#define BB 4
#define SS 2048
#define EE 256
#define HH 8
#define DK 32
#define MM (BB * SS)
#define KK EE
#define NN EE

#define QT 128            // query tile rows per block
#define JT 64             // key tile cols per iteration
#define NQT (SS / QT)     // 16 query tiles

// Scratch (device globals; no allocation allowed)
__device__ float g_qh[BB * HH * SS * DK];   // [B,H,S,DK]
__device__ float g_kh[BB * HH * SS * DK];
__device__ float g_vh[BB * HH * SS * DK];
__device__ float g_ao[BB * SS * EE];        // attention output [B,S,H*DK]

// ---------------------------------------------------------------------------
// f32x2 packed helpers (Blackwell FFMA2)
// ---------------------------------------------------------------------------
__device__ __forceinline__ unsigned long long ffma2(unsigned long long a,
                                                    unsigned long long b,
                                                    unsigned long long c)
{
    unsigned long long d;
    asm("fma.rn.f32x2 %0, %1, %2, %3;" : "=l"(d) : "l"(a), "l"(b), "l"(c));
    return d;
}
__device__ __forceinline__ float2 u2f(unsigned long long v)
{
    float2 r;
    asm("mov.b64 {%0, %1}, %2;" : "=f"(r.x), "=f"(r.y) : "l"(v));
    return r;
}
__device__ __forceinline__ unsigned long long pack2(float x)
{
    unsigned long long d;
    asm("mov.b64 %0, {%1, %1};" : "=l"(d) : "f"(x));
    return d;
}
__device__ __forceinline__ unsigned long long mul2(unsigned long long a,
                                                   unsigned long long b)
{
    unsigned long long d;
    asm("mul.rn.f32x2 %0, %1, %2;" : "=l"(d) : "l"(a), "l"(b));
    return d;
}

// 16-lane (tx-group) reductions; xor offsets stay within each 16-lane half
__device__ __forceinline__ float redmax16(float v)
{
#pragma unroll
    for (int off = 8; off > 0; off >>= 1)
        v = fmaxf(v, __shfl_xor_sync(0xffffffffu, v, off, 32));
    return v;
}
__device__ __forceinline__ float redsum16(float v)
{
#pragma unroll
    for (int off = 8; off > 0; off >>= 1)
        v += __shfl_xor_sync(0xffffffffu, v, off, 32);
    return v;
}

// ---------------------------------------------------------------------------
// GEMM: C[M,N] = X[M,K] @ W[N,K]^T + bias[N]
// Thread outputs: rows m0+ty*4+y (y<4), cols n0+tx+16x (x<4).
// B-operand lanes stride 1 row (pitch 36 -> 2-phase floor); A is broadcast.
// ---------------------------------------------------------------------------
__global__ void gemm_bias_kernel(const float* __restrict__ X,
                                 const float* __restrict__ W,
                                 const float* __restrict__ bias,
                                 float* __restrict__ out,
                                 int permute)
{
    __shared__ float Xs[64][36];
    __shared__ float Ws[64][36];

    const int tid = threadIdx.x;
    const int tx = tid & 15;
    const int ty = tid >> 4;
    const int m0 = blockIdx.x * 64;
    const int n0 = blockIdx.y * 64;

    unsigned long long acc2[4][4];
#pragma unroll
    for (int y = 0; y < 4; y++)
#pragma unroll
        for (int x = 0; x < 4; x++) acc2[y][x] = 0ULL;

    for (int t = 0; t < KK / 32; t++) {
        const int k0 = t * 32;
        __syncthreads();
#pragma unroll
        for (int l = 0; l < 2; l++) {
            int idx = tid + l * 256;
            int r = idx >> 3;
            int c4 = (idx & 7) * 4;
            *(float4*)&Xs[r][c4] = *(const float4*)&X[(size_t)(m0 + r) * KK + k0 + c4];
            *(float4*)&Ws[r][c4] = *(const float4*)&W[(size_t)(n0 + r) * KK + k0 + c4];
        }
        __syncthreads();

#pragma unroll
        for (int m2 = 0; m2 < 8; m2++) {
            ulonglong2 a[4], b[4];
#pragma unroll
            for (int y = 0; y < 4; y++)
                a[y] = *(const ulonglong2*)&Xs[ty * 4 + y][m2 * 4];
#pragma unroll
            for (int x = 0; x < 4; x++)
                b[x] = *(const ulonglong2*)&Ws[tx + 16 * x][m2 * 4];
#pragma unroll
            for (int y = 0; y < 4; y++)
#pragma unroll
                for (int x = 0; x < 4; x++) {
                    acc2[y][x] = ffma2(a[y].x, b[x].x, acc2[y][x]);
                    acc2[y][x] = ffma2(a[y].y, b[x].y, acc2[y][x]);
                }
        }
    }

#pragma unroll
    for (int y = 0; y < 4; y++) {
#pragma unroll
        for (int x = 0; x < 4; x++) {
            int m = m0 + ty * 4 + y;
            int n = n0 + tx + 16 * x;
            float2 f = u2f(acc2[y][x]);
            float val = f.x + f.y + bias[n];
            if (permute) {
                int b_ = m >> 11;
                int s_ = m & 2047;
                int h_ = n >> 5;
                int d_ = n & 31;
                out[(((size_t)b_ * HH + h_) * SS + s_) * DK + d_] = val;
            } else {
                out[(size_t)m * NN + n] = val;
            }
        }
    }
}

// ---------------------------------------------------------------------------
// Tiled attention with distance-decay.
// Block: 128 query rows of one (b,h). tx=tid&15, ty=tid>>4.
// Thread score cols: c = tx + 16x (x<4); rows r0..r0+7 (r0=ty*8).
// ps / Vst use permuted column positions pos = 4*(c&15) + (c>>4).
// ---------------------------------------------------------------------------
struct AttnSmem {
    float Qs[128][36];    // [r][k]
    float Ks[64][36];     // [c][k]
    float Vst[32][68];    // [d][pos]
    float ps[128][68];    // [r][pos]
};

__device__ __forceinline__ void compute_scores_f2(
    const AttnSmem* S, int r0, int tx, int i0, int j0,
    float scale, bool need_mask, float scr[8][4])
{
#pragma unroll
    for (int yh = 0; yh < 2; yh++) {
        unsigned long long s2[4][4];
#pragma unroll
        for (int y = 0; y < 4; y++)
#pragma unroll
            for (int x = 0; x < 4; x++) s2[y][x] = 0ULL;

#pragma unroll
        for (int m2 = 0; m2 < 8; m2++) {
            ulonglong2 a[4], b[4];
#pragma unroll
            for (int y = 0; y < 4; y++)
                a[y] = *(const ulonglong2*)&S->Qs[r0 + yh * 4 + y][m2 * 4];
#pragma unroll
            for (int x = 0; x < 4; x++)
                b[x] = *(const ulonglong2*)&S->Ks[tx + 16 * x][m2 * 4];
#pragma unroll
            for (int y = 0; y < 4; y++)
#pragma unroll
                for (int x = 0; x < 4; x++) {
                    s2[y][x] = ffma2(a[y].x, b[x].x, s2[y][x]);
                    s2[y][x] = ffma2(a[y].y, b[x].y, s2[y][x]);
                }
        }
#pragma unroll
        for (int y = 0; y < 4; y++)
#pragma unroll
            for (int x = 0; x < 4; x++) {
                float2 f = u2f(s2[y][x]);
                scr[yh * 4 + y][x] = (f.x + f.y) * scale;
            }
    }

    if (need_mask) {
#pragma unroll
        for (int y = 0; y < 8; y++) {
            int i = i0 + r0 + y;
#pragma unroll
            for (int x = 0; x < 4; x++)
                if (j0 + tx + 16 * x > i) scr[y][x] = -1e30f;
        }
    }
}

__global__ __launch_bounds__(256, 2)
void attn_tile_kernel(const float* __restrict__ qh,
                      const float* __restrict__ kh,
                      const float* __restrict__ vh,
                      const float* __restrict__ gammas,
                      float* __restrict__ ao)
{
    extern __shared__ char smem_raw[];
    AttnSmem* S = (AttnSmem*)smem_raw;

    const int tid = threadIdx.x;
    const int tx = tid & 15;
    const int ty = tid >> 4;
    const int r0 = ty * 8;

    // heavy q-tiles launch first
    const int qt = (NQT - 1) - (blockIdx.x >> 5);
    const int bh = blockIdx.x & 31;
    const int h = bh & (HH - 1);
    const int b = bh >> 3;
    const int i0 = qt * QT;
    const int jtiles = 2 * qt + 2;

    const float* qbase = qh + (size_t)bh * SS * DK;
    const float* kbase = kh + (size_t)bh * SS * DK;
    const float* vbase = vh + (size_t)bh * SS * DK;

    const float g = gammas[h];
    const float gamma = -log1pf(__expf(g));
    const float scale = 0.17677669529663687f;  // 1/sqrt(32)

    // ---- load Q tile ----
#pragma unroll
    for (int l = 0; l < 4; l++) {
        int idx = tid + l * 256;
        int r = idx >> 3;
        int kq = (idx & 7) * 4;
        *(float4*)&S->Qs[r][kq] = *(const float4*)(qbase + (size_t)(i0 + r) * DK + kq);
    }

    float rm1[8], rs1[8];
#pragma unroll
    for (int y = 0; y < 8; y++) { rm1[y] = -3.0e38f; rs1[y] = 0.f; }

    float scr[8][4];

    // =================== PASS 1: softmax-1 stats ===================
    for (int jt = 0; jt < jtiles; jt++) {
        const int j0 = jt * JT;
        __syncthreads();
#pragma unroll
        for (int l = 0; l < 2; l++) {
            int idx = tid + l * 256;
            int c = idx >> 3;
            int kq = (idx & 7) * 4;
            *(float4*)&S->Ks[c][kq] = *(const float4*)(kbase + (size_t)(j0 + c) * DK + kq);
        }
        __syncthreads();

        compute_scores_f2(S, r0, tx, i0, j0, scale, (j0 + JT - 1 > i0), scr);

#pragma unroll
        for (int y = 0; y < 8; y++) {
            float lm = fmaxf(fmaxf(scr[y][0], scr[y][1]), fmaxf(scr[y][2], scr[y][3]));
            float tm = redmax16(lm);
            float nm = fmaxf(rm1[y], tm);
            float f = __expf(rm1[y] - nm);
            rm1[y] = nm;
            float pe = __expf(scr[y][0] - nm) + __expf(scr[y][1] - nm) +
                       __expf(scr[y][2] - nm) + __expf(scr[y][3] - nm);
            rs1[y] = rs1[y] * f + redsum16(pe);
        }
    }

    float ri1[8];
#pragma unroll
    for (int y = 0; y < 8; y++) ri1[y] = 1.f / rs1[y];

    float rm2[8], rl2[8], rcarry[8];
    unsigned long long acc2[8][2];
#pragma unroll
    for (int y = 0; y < 8; y++) {
        rm2[y] = -3.0e38f; rl2[y] = 0.f; rcarry[y] = 0.f;
        acc2[y][0] = 0ULL; acc2[y][1] = 0ULL;
    }

    // =================== PASS 2: decay + softmax-2 + PV ===================
    for (int jt = 0; jt < jtiles; jt++) {
        const int j0 = jt * JT;
        __syncthreads();   // prev PV done reading Vst / ps; pass-1 Ks done
#pragma unroll
        for (int l = 0; l < 2; l++) {
            int idx = tid + l * 256;
            int c = idx >> 3;
            int kq = (idx & 7) * 4;
            *(float4*)&S->Ks[c][kq] = *(const float4*)(kbase + (size_t)(j0 + c) * DK + kq);
            float4 vv = *(const float4*)(vbase + (size_t)(j0 + c) * DK + kq);
            int pc = 4 * (c & 15) + (c >> 4);   // permuted column position
            S->Vst[kq + 0][pc] = vv.x;
            S->Vst[kq + 1][pc] = vv.y;
            S->Vst[kq + 2][pc] = vv.z;
            S->Vst[kq + 3][pc] = vv.w;
        }
        __syncthreads();

        compute_scores_f2(S, r0, tx, i0, j0, scale, (j0 + JT - 1 > i0), scr);

#pragma unroll
        for (int y = 0; y < 8; y++) {
            const int i = i0 + r0 + y;
            const float m1 = rm1[y], is1 = ri1[y];

            // normalized s1 per column (cols ordered j = 16x + tx)
            float e[4];
#pragma unroll
            for (int x = 0; x < 4; x++) e[x] = __expf(scr[y][x] - m1) * is1;

            // x-major inclusive cumsum: 4 sub-scans over the 16-lane group
            float basec = rcarry[y];
            float cums[4];
#pragma unroll
            for (int x = 0; x < 4; x++) {
                float run = e[x];
#pragma unroll
                for (int off = 1; off < 16; off <<= 1) {
                    float v = __shfl_up_sync(0xffffffffu, run, off, 16);
                    if (tx >= off) run += v;
                }
                cums[x] = basec + run;
                basec += __shfl_sync(0xffffffffu, run, 15, 16);
            }
            rcarry[y] = basec;

            // distance-decay rescale
            float s2v[4];
#pragma unroll
            for (int x = 0; x < 4; x++) {
                int j = j0 + tx + 16 * x;
                float rem = 1.f - cums[x];
                float posn = fabsf((float)(i - j));
                float dist = sqrtf(fmaxf(rem * posn, 0.f));
                float eff = fmaxf(__expf(dist * gamma), 1e-5f);  // exp<=1: no upper clip
                s2v[x] = scr[y][x] * eff;
            }

            // online softmax-2
            float lm = fmaxf(fmaxf(s2v[0], s2v[1]), fmaxf(s2v[2], s2v[3]));
            float tm = redmax16(lm);
            float nm = fmaxf(rm2[y], tm);
            float f = __expf(rm2[y] - nm);
            rm2[y] = nm;
            float p0 = __expf(s2v[0] - nm);
            float p1 = __expf(s2v[1] - nm);
            float p2 = __expf(s2v[2] - nm);
            float p3 = __expf(s2v[3] - nm);
            rl2[y] = rl2[y] * f + redsum16(p0 + p1 + p2 + p3);

            unsigned long long pf = pack2(f);
            acc2[y][0] = mul2(acc2[y][0], pf);
            acc2[y][1] = mul2(acc2[y][1], pf);

            // permuted store: position 4*tx+x holds col tx+16x
            *(float4*)&S->ps[r0 + y][4 * tx] = make_float4(p0, p1, p2, p3);
        }
        __syncwarp();   // ps rows produced/consumed within the same 16-lane group

        // PV: acc dims d = tx and tx+16; positions align with Vst permutation
#pragma unroll 4
        for (int cq = 0; cq < 16; cq++) {
            ulonglong2 v0 = *(const ulonglong2*)&S->Vst[tx][cq * 4];
            ulonglong2 v1 = *(const ulonglong2*)&S->Vst[tx + 16][cq * 4];
#pragma unroll
            for (int y = 0; y < 8; y++) {
                ulonglong2 pp = *(const ulonglong2*)&S->ps[r0 + y][cq * 4];
                acc2[y][0] = ffma2(pp.x, v0.x, acc2[y][0]);
                acc2[y][0] = ffma2(pp.y, v0.y, acc2[y][0]);
                acc2[y][1] = ffma2(pp.x, v1.x, acc2[y][1]);
                acc2[y][1] = ffma2(pp.y, v1.y, acc2[y][1]);
            }
        }
    }

    // ---- write output ----
#pragma unroll
    for (int y = 0; y < 8; y++) {
        int i = i0 + r0 + y;
        float inv = 1.f / rl2[y];
        float2 a0 = u2f(acc2[y][0]);
        float2 a1 = u2f(acc2[y][1]);
        size_t base = ((size_t)b * SS + i) * EE + h * DK;
        ao[base + tx] = (a0.x + a0.y) * inv;
        ao[base + tx + 16] = (a1.x + a1.y) * inv;
    }
}

// ---------------------------------------------------------------------------
extern "C" void kernel_launch(void* const* d_in, const int* in_sizes, int n_in,
                              void* d_out, int out_size)
{
    const float* q      = (const float*)d_in[0];
    const float* k      = (const float*)d_in[1];
    const float* v      = (const float*)d_in[2];
    // d_in[3] = mask (unused; causal structure known)
    const float* Wq     = (const float*)d_in[4];
    const float* bq     = (const float*)d_in[5];
    const float* Wk     = (const float*)d_in[6];
    const float* bk     = (const float*)d_in[7];
    const float* Wv     = (const float*)d_in[8];
    const float* bv     = (const float*)d_in[9];
    const float* Wo     = (const float*)d_in[10];
    const float* bo     = (const float*)d_in[11];
    const float* gammas = (const float*)d_in[12];
    float* out = (float*)d_out;

    float *qh, *kh, *vh, *ao;
    cudaGetSymbolAddress((void**)&qh, g_qh);
    cudaGetSymbolAddress((void**)&kh, g_kh);
    cudaGetSymbolAddress((void**)&vh, g_vh);
    cudaGetSymbolAddress((void**)&ao, g_ao);

    static bool attr_set = false;
    if (!attr_set) {
        cudaFuncSetAttribute(attn_tile_kernel,
                             cudaFuncAttributeMaxDynamicSharedMemorySize,
                             (int)sizeof(AttnSmem));
        attr_set = true;
    }

    dim3 gblk(256);
    dim3 ggrid(MM / 64, NN / 64);

    gemm_bias_kernel<<<ggrid, gblk>>>(q, Wq, bq, qh, 1);
    gemm_bias_kernel<<<ggrid, gblk>>>(k, Wk, bk, kh, 1);
    gemm_bias_kernel<<<ggrid, gblk>>>(v, Wv, bv, vh, 1);

    attn_tile_kernel<<<BB * HH * NQT, 256, sizeof(AttnSmem)>>>(qh, kh, vh, gammas, ao);

    gemm_bias_kernel<<<ggrid, gblk>>>(ao, Wo, bo, out, 0);
}

// round 11
// speedup vs baseline: 1.4216x; 1.2487x over previous
#include <cuda_runtime.h>
#include <cuda_bf16.h>
#include <math.h>

// Problem constants
#define BB 4
#define SS 2048
#define EE 256
#define HH 8
#define DK 32
#define MM (BB * SS)
#define KK EE
#define NN EE

#define QT 128            // query tile rows per block
#define JT 64             // key tile cols per iteration
#define NQT (SS / QT)     // 16 query tiles

// Scratch (device globals; no allocation allowed)
__device__ float g_qh[BB * HH * SS * DK];   // [B,H,S,DK]
__device__ float g_kh[BB * HH * SS * DK];
__device__ float g_vh[BB * HH * SS * DK];
__device__ float g_ao[BB * SS * EE];        // attention output [B,S,H*DK]

// ---------------------------------------------------------------------------
// f32x2 packed helpers (Blackwell FFMA2) — used in the projection GEMMs only
// ---------------------------------------------------------------------------
__device__ __forceinline__ unsigned long long ffma2(unsigned long long a,
                                                    unsigned long long b,
                                                    unsigned long long c)
{
    unsigned long long d;
    asm("fma.rn.f32x2 %0, %1, %2, %3;" : "=l"(d) : "l"(a), "l"(b), "l"(c));
    return d;
}
__device__ __forceinline__ float2 u2f(unsigned long long v)
{
    float2 r;
    asm("mov.b64 {%0, %1}, %2;" : "=f"(r.x), "=f"(r.y) : "l"(v));
    return r;
}

// ---------------------------------------------------------------------------
// GEMM (R9 version, measured 142us for all four): C = X @ W^T + bias
// Thread outputs: rows m0+ty*4+y (y<4), cols n0+tx+16x (x<4).
// ---------------------------------------------------------------------------
__global__ void gemm_bias_kernel(const float* __restrict__ X,
                                 const float* __restrict__ W,
                                 const float* __restrict__ bias,
                                 float* __restrict__ out,
                                 int permute)
{
    __shared__ float Xs[64][36];
    __shared__ float Ws[64][36];

    const int tid = threadIdx.x;
    const int tx = tid & 15;
    const int ty = tid >> 4;
    const int m0 = blockIdx.x * 64;
    const int n0 = blockIdx.y * 64;

    unsigned long long acc2[4][4];
#pragma unroll
    for (int y = 0; y < 4; y++)
#pragma unroll
        for (int x = 0; x < 4; x++) acc2[y][x] = 0ULL;

    for (int t = 0; t < KK / 32; t++) {
        const int k0 = t * 32;
        __syncthreads();
#pragma unroll
        for (int l = 0; l < 2; l++) {
            int idx = tid + l * 256;
            int r = idx >> 3;
            int c4 = (idx & 7) * 4;
            *(float4*)&Xs[r][c4] = *(const float4*)&X[(size_t)(m0 + r) * KK + k0 + c4];
            *(float4*)&Ws[r][c4] = *(const float4*)&W[(size_t)(n0 + r) * KK + k0 + c4];
        }
        __syncthreads();

#pragma unroll
        for (int m2 = 0; m2 < 8; m2++) {
            ulonglong2 a[4], b[4];
#pragma unroll
            for (int y = 0; y < 4; y++)
                a[y] = *(const ulonglong2*)&Xs[ty * 4 + y][m2 * 4];
#pragma unroll
            for (int x = 0; x < 4; x++)
                b[x] = *(const ulonglong2*)&Ws[tx + 16 * x][m2 * 4];
#pragma unroll
            for (int y = 0; y < 4; y++)
#pragma unroll
                for (int x = 0; x < 4; x++) {
                    acc2[y][x] = ffma2(a[y].x, b[x].x, acc2[y][x]);
                    acc2[y][x] = ffma2(a[y].y, b[x].y, acc2[y][x]);
                }
        }
    }

#pragma unroll
    for (int y = 0; y < 4; y++) {
#pragma unroll
        for (int x = 0; x < 4; x++) {
            int m = m0 + ty * 4 + y;
            int n = n0 + tx + 16 * x;
            float2 f = u2f(acc2[y][x]);
            float val = f.x + f.y + bias[n];
            if (permute) {
                int b_ = m >> 11;
                int s_ = m & 2047;
                int h_ = n >> 5;
                int d_ = n & 31;
                out[(((size_t)b_ * HH + h_) * SS + s_) * DK + d_] = val;
            } else {
                out[(size_t)m * NN + n] = val;
            }
        }
    }
}

// ---------------------------------------------------------------------------
// Tiled attention with distance-decay (R5 datapath, reduced reduction cost).
// Block: 128 query rows of one (b,h). tx=tid&15 (cols c0=4tx..), ty=tid>>4
// (rows r0=8ty..).
// ---------------------------------------------------------------------------
struct AttnSmem {
    float Qs[32][132];    // [k][r]  query tile, transposed
    float Ks[32][68];     // [k][c]  key tile, transposed
    float Vst[32][68];    // [d][c]  value tile, transposed
    float ps[128][68];    // prefix vals, then p2 tile
    float rowA[128][17];  // cross-thread combine buffer
    float rowB[128][17];
    float m1s[128];
    float s1s[128];
    float l2s[128];
    float carry[128];
};

__device__ __forceinline__ void compute_scores(
    const AttnSmem* S, int r0, int c0, int i0, int j0,
    float scale, float scr[8][4])
{
#pragma unroll
    for (int y = 0; y < 8; y++)
#pragma unroll
        for (int x = 0; x < 4; x++) scr[y][x] = 0.f;

#pragma unroll
    for (int k = 0; k < 32; k++) {
        float4 a0 = *(const float4*)&S->Qs[k][r0];
        float4 a1 = *(const float4*)&S->Qs[k][r0 + 4];
        float4 bb = *(const float4*)&S->Ks[k][c0];
        float a[8] = {a0.x, a0.y, a0.z, a0.w, a1.x, a1.y, a1.z, a1.w};
        float b[4] = {bb.x, bb.y, bb.z, bb.w};
#pragma unroll
        for (int y = 0; y < 8; y++)
#pragma unroll
            for (int x = 0; x < 4; x++) scr[y][x] += a[y] * b[x];
    }
    // scale + causal mask
    bool need_mask = (j0 + JT - 1 > i0);
#pragma unroll
    for (int y = 0; y < 8; y++) {
        int i = i0 + r0 + y;
#pragma unroll
        for (int x = 0; x < 4; x++) {
            scr[y][x] *= scale;
            if (need_mask && (j0 + c0 + x > i)) scr[y][x] = -1e30f;
        }
    }
}

__global__ __launch_bounds__(256, 2)
void attn_tile_kernel(const float* __restrict__ qh,
                      const float* __restrict__ kh,
                      const float* __restrict__ vh,
                      const float* __restrict__ gammas,
                      float* __restrict__ ao)
{
    extern __shared__ char smem_raw[];
    AttnSmem* S = (AttnSmem*)smem_raw;

    const int tid = threadIdx.x;
    const int tx = tid & 15;
    const int ty = tid >> 4;
    const int r0 = ty * 8;
    const int c0 = tx * 4;

    // heavy q-tiles launch first
    const int qt = (NQT - 1) - (blockIdx.x >> 5);
    const int bh = blockIdx.x & 31;
    const int h = bh & (HH - 1);
    const int b = bh >> 3;
    const int i0 = qt * QT;
    const int jtiles = 2 * qt + 2;

    const float* qbase = qh + (size_t)bh * SS * DK;
    const float* kbase = kh + (size_t)bh * SS * DK;
    const float* vbase = vh + (size_t)bh * SS * DK;

    const float g = gammas[h];
    const float gamma = -log1pf(__expf(g));
    const float scale = 0.17677669529663687f;  // 1/sqrt(32)

    // ---- load Q tile (transposed) ----
#pragma unroll
    for (int l = 0; l < 4; l++) {
        int idx = tid + l * 256;
        int r = idx >> 3;
        int kq = (idx & 7) * 4;
        float4 qv = *(const float4*)(qbase + (size_t)(i0 + r) * DK + kq);
        S->Qs[kq + 0][r] = qv.x;
        S->Qs[kq + 1][r] = qv.y;
        S->Qs[kq + 2][r] = qv.z;
        S->Qs[kq + 3][r] = qv.w;
    }

    // per-thread (register-only) online softmax-1 stats over own 4-col subset
    float rm1[8], rs1[8];
#pragma unroll
    for (int y = 0; y < 8; y++) { rm1[y] = -3.0e38f; rs1[y] = 0.f; }

    float scr[8][4];

    // =================== PASS 1: softmax-1 stats (no per-tile reductions) ==
    for (int jt = 0; jt < jtiles; jt++) {
        const int j0 = jt * JT;
        __syncthreads();
#pragma unroll
        for (int l = 0; l < 2; l++) {
            int idx = tid + l * 256;
            int c = idx >> 3;
            int kq = (idx & 7) * 4;
            float4 kv = *(const float4*)(kbase + (size_t)(j0 + c) * DK + kq);
            S->Ks[kq + 0][c] = kv.x;
            S->Ks[kq + 1][c] = kv.y;
            S->Ks[kq + 2][c] = kv.z;
            S->Ks[kq + 3][c] = kv.w;
        }
        __syncthreads();

        compute_scores(S, r0, c0, i0, j0, scale, scr);

#pragma unroll
        for (int y = 0; y < 8; y++) {
            float lm = fmaxf(fmaxf(scr[y][0], scr[y][1]), fmaxf(scr[y][2], scr[y][3]));
            float nm = fmaxf(rm1[y], lm);
            float f = __expf(rm1[y] - nm);
            float pe = __expf(scr[y][0] - nm) + __expf(scr[y][1] - nm) +
                       __expf(scr[y][2] - nm) + __expf(scr[y][3] - nm);
            rs1[y] = rs1[y] * f + pe;
            rm1[y] = nm;
        }
    }

    // ---- single cross-thread combine of the 16 (m,s) partials per row ----
#pragma unroll
    for (int y = 0; y < 8; y++) {
        S->rowA[r0 + y][tx] = rm1[y];
        S->rowB[r0 + y][tx] = rs1[y];
    }
    __syncthreads();
    if (tid < QT) {
        int r = tid;
        float nm = -3.0e38f;
#pragma unroll
        for (int t = 0; t < 16; t++) nm = fmaxf(nm, S->rowA[r][t]);
        float s = 0.f;
#pragma unroll
        for (int t = 0; t < 16; t++) s += S->rowB[r][t] * __expf(S->rowA[r][t] - nm);
        S->m1s[r] = nm;
        S->s1s[r] = s;
        S->carry[r] = 0.f;
    }
    __syncthreads();

    float ri1[8], rM[8], rl2[8];
    float acc[8][2];
#pragma unroll
    for (int y = 0; y < 8; y++) {
        rm1[y] = S->m1s[r0 + y];
        ri1[y] = 1.f / S->s1s[r0 + y];
        rM[y] = fmaxf(rm1[y], 0.f);   // fixed softmax-2 reference (eff<=1 => s2<=max(m1,0))
        rl2[y] = 0.f;
        acc[y][0] = 0.f;
        acc[y][1] = 0.f;
    }

    // =================== PASS 2: decay + fixed-ref softmax-2 + PV ==========
    for (int jt = 0; jt < jtiles; jt++) {
        const int j0 = jt * JT;
        __syncthreads();   // prev PV done reading Vst/ps
#pragma unroll
        for (int l = 0; l < 2; l++) {
            int idx = tid + l * 256;
            int c = idx >> 3;
            int kq = (idx & 7) * 4;
            float4 kv = *(const float4*)(kbase + (size_t)(j0 + c) * DK + kq);
            S->Ks[kq + 0][c] = kv.x;
            S->Ks[kq + 1][c] = kv.y;
            S->Ks[kq + 2][c] = kv.z;
            S->Ks[kq + 3][c] = kv.w;
            float4 vv = *(const float4*)(vbase + (size_t)(j0 + c) * DK + kq);
            S->Vst[kq + 0][c] = vv.x;
            S->Vst[kq + 1][c] = vv.y;
            S->Vst[kq + 2][c] = vv.z;
            S->Vst[kq + 3][c] = vv.w;
        }
        __syncthreads();

        compute_scores(S, r0, c0, i0, j0, scale, scr);

        // normalized s1 chunk prefix -> ps, chunk totals -> rowA
#pragma unroll
        for (int y = 0; y < 8; y++) {
            float m = rm1[y], is = ri1[y];
            float e0 = __expf(scr[y][0] - m) * is;
            float e1 = __expf(scr[y][1] - m) * is;
            float e2 = __expf(scr[y][2] - m) * is;
            float e3 = __expf(scr[y][3] - m) * is;
            float q1 = e0, q2 = q1 + e1, q3 = q2 + e2, q4 = q3 + e3;
            *(float4*)&S->ps[r0 + y][c0] = make_float4(q1, q2, q3, q4);
            S->rowA[r0 + y][tx] = q4;
        }
        __syncthreads();
        // sequential scan of 16 chunk totals per row + carry
        if (tid < QT) {
            int r = tid;
            float run = S->carry[r];
#pragma unroll
            for (int t = 0; t < 16; t++) {
                float tmp = S->rowA[r][t];
                S->rowA[r][t] = run;
                run += tmp;
            }
            S->carry[r] = run;
        }
        __syncthreads();

        // decay rescale + p = exp(s2 - M); l2 partial stays in registers
#pragma unroll
        for (int y = 0; y < 8; y++) {
            const int i = i0 + r0 + y;
            float excl = S->rowA[r0 + y][tx];
            float4 pre = *(const float4*)&S->ps[r0 + y][c0];
            float cums[4] = {excl + pre.x, excl + pre.y, excl + pre.z, excl + pre.w};
            float p[4];
#pragma unroll
            for (int x = 0; x < 4; x++) {
                int j = j0 + c0 + x;
                float rem = 1.f - cums[x];
                float posn = fabsf((float)(i - j));
                float dist = sqrtf(fmaxf(rem * posn, 0.f));
                float eff = fmaxf(__expf(dist * gamma), 1e-5f);  // exp<=1: no upper clip
                p[x] = __expf(scr[y][x] * eff - rM[y]);
            }
            rl2[y] += (p[0] + p[1]) + (p[2] + p[3]);
            *(float4*)&S->ps[r0 + y][c0] = make_float4(p[0], p[1], p[2], p[3]);
        }
        __syncwarp();   // ps rows produced/consumed within the same half-warp

        // PV: out[r][d] += sum_c p[r][c] * V[c][d]
        const int d0 = 2 * tx;
#pragma unroll 4
        for (int cb = 0; cb < 16; cb++) {
            float4 v0 = *(const float4*)&S->Vst[d0][cb * 4];
            float4 v1 = *(const float4*)&S->Vst[d0 + 1][cb * 4];
#pragma unroll
            for (int y = 0; y < 8; y++) {
                float4 pp = *(const float4*)&S->ps[r0 + y][cb * 4];
                acc[y][0] += pp.x * v0.x + pp.y * v0.y + pp.z * v0.z + pp.w * v0.w;
                acc[y][1] += pp.x * v1.x + pp.y * v1.y + pp.z * v1.z + pp.w * v1.w;
            }
        }
    }

    // ---- combine l2 partials once, then write output ----
#pragma unroll
    for (int y = 0; y < 8; y++) S->rowA[r0 + y][tx] = rl2[y];
    __syncthreads();
    if (tid < QT) {
        int r = tid;
        float s = 0.f;
#pragma unroll
        for (int t = 0; t < 16; t++) s += S->rowA[r][t];
        S->l2s[r] = s;
    }
    __syncthreads();

#pragma unroll
    for (int y = 0; y < 8; y++) {
        int i = i0 + r0 + y;
        float inv = 1.f / S->l2s[r0 + y];
        size_t base = ((size_t)b * SS + i) * EE + h * DK + 2 * tx;
        ao[base] = acc[y][0] * inv;
        ao[base + 1] = acc[y][1] * inv;
    }
}

// ---------------------------------------------------------------------------
extern "C" void kernel_launch(void* const* d_in, const int* in_sizes, int n_in,
                              void* d_out, int out_size)
{
    const float* q      = (const float*)d_in[0];
    const float* k      = (const float*)d_in[1];
    const float* v      = (const float*)d_in[2];
    // d_in[3] = mask (unused; causal structure known)
    const float* Wq     = (const float*)d_in[4];
    const float* bq     = (const float*)d_in[5];
    const float* Wk     = (const float*)d_in[6];
    const float* bk     = (const float*)d_in[7];
    const float* Wv     = (const float*)d_in[8];
    const float* bv     = (const float*)d_in[9];
    const float* Wo     = (const float*)d_in[10];
    const float* bo     = (const float*)d_in[11];
    const float* gammas = (const float*)d_in[12];
    float* out = (float*)d_out;

    float *qh, *kh, *vh, *ao;
    cudaGetSymbolAddress((void**)&qh, g_qh);
    cudaGetSymbolAddress((void**)&kh, g_kh);
    cudaGetSymbolAddress((void**)&vh, g_vh);
    cudaGetSymbolAddress((void**)&ao, g_ao);

    static bool attr_set = false;
    if (!attr_set) {
        cudaFuncSetAttribute(attn_tile_kernel,
                             cudaFuncAttributeMaxDynamicSharedMemorySize,
                             (int)sizeof(AttnSmem));
        attr_set = true;
    }

    dim3 gblk(256);
    dim3 ggrid(MM / 64, NN / 64);

    gemm_bias_kernel<<<ggrid, gblk>>>(q, Wq, bq, qh, 1);
    gemm_bias_kernel<<<ggrid, gblk>>>(k, Wk, bk, kh, 1);
    gemm_bias_kernel<<<ggrid, gblk>>>(v, Wv, bv, vh, 1);

    attn_tile_kernel<<<BB * HH * NQT, 256, sizeof(AttnSmem)>>>(qh, kh, vh, gammas, ao);

    gemm_bias_kernel<<<ggrid, gblk>>>(ao, Wo, bo, out, 0);
}

// round 16
// speedup vs baseline: 1.5926x; 1.1203x over previous
#include <cuda_runtime.h>
#include <cuda_bf16.h>
#include <math.h>

// Problem constants
#define BB 4
#define SS 2048
#define EE 256
#define HH 8
#define DK 32
#define MM (BB * SS)
#define KK EE
#define NN EE

#define QT 128            // query tile rows per block
#define JT 64             // key tile cols per iteration
#define NQT (SS / QT)     // 16 query tiles

// Scratch (device globals; no allocation allowed)
__device__ float g_qh[BB * HH * SS * DK];   // [B,H,S,DK]
__device__ float g_kh[BB * HH * SS * DK];
__device__ float g_vh[BB * HH * SS * DK];
__device__ float g_ao[BB * SS * EE];        // attention output [B,S,H*DK]

// ---------------------------------------------------------------------------
// fast-math helpers
// ---------------------------------------------------------------------------
__device__ __forceinline__ float ex2(float x)
{
    float y;
    asm("ex2.approx.ftz.f32 %0, %1;" : "=f"(y) : "f"(x));
    return y;
}
__device__ __forceinline__ float sqrt_approx(float x)
{
    float y;
    asm("sqrt.approx.ftz.f32 %0, %1;" : "=f"(y) : "f"(x));
    return y;
}

// ---------------------------------------------------------------------------
// f32x2 packed helpers (Blackwell FFMA2) — projection GEMMs
// ---------------------------------------------------------------------------
__device__ __forceinline__ unsigned long long ffma2(unsigned long long a,
                                                    unsigned long long b,
                                                    unsigned long long c)
{
    unsigned long long d;
    asm("fma.rn.f32x2 %0, %1, %2, %3;" : "=l"(d) : "l"(a), "l"(b), "l"(c));
    return d;
}
__device__ __forceinline__ float2 u2f(unsigned long long v)
{
    float2 r;
    asm("mov.b64 {%0, %1}, %2;" : "=f"(r.x), "=f"(r.y) : "l"(v));
    return r;
}

// ---------------------------------------------------------------------------
// GEMM (R9/R11 version, measured ~142us for all four): C = X @ W^T + bias
// ---------------------------------------------------------------------------
__global__ void gemm_bias_kernel(const float* __restrict__ X,
                                 const float* __restrict__ W,
                                 const float* __restrict__ bias,
                                 float* __restrict__ out,
                                 int permute)
{
    __shared__ float Xs[64][36];
    __shared__ float Ws[64][36];

    const int tid = threadIdx.x;
    const int tx = tid & 15;
    const int ty = tid >> 4;
    const int m0 = blockIdx.x * 64;
    const int n0 = blockIdx.y * 64;

    unsigned long long acc2[4][4];
#pragma unroll
    for (int y = 0; y < 4; y++)
#pragma unroll
        for (int x = 0; x < 4; x++) acc2[y][x] = 0ULL;

    for (int t = 0; t < KK / 32; t++) {
        const int k0 = t * 32;
        __syncthreads();
#pragma unroll
        for (int l = 0; l < 2; l++) {
            int idx = tid + l * 256;
            int r = idx >> 3;
            int c4 = (idx & 7) * 4;
            *(float4*)&Xs[r][c4] = *(const float4*)&X[(size_t)(m0 + r) * KK + k0 + c4];
            *(float4*)&Ws[r][c4] = *(const float4*)&W[(size_t)(n0 + r) * KK + k0 + c4];
        }
        __syncthreads();

#pragma unroll
        for (int m2 = 0; m2 < 8; m2++) {
            ulonglong2 a[4], b[4];
#pragma unroll
            for (int y = 0; y < 4; y++)
                a[y] = *(const ulonglong2*)&Xs[ty * 4 + y][m2 * 4];
#pragma unroll
            for (int x = 0; x < 4; x++)
                b[x] = *(const ulonglong2*)&Ws[tx + 16 * x][m2 * 4];
#pragma unroll
            for (int y = 0; y < 4; y++)
#pragma unroll
                for (int x = 0; x < 4; x++) {
                    acc2[y][x] = ffma2(a[y].x, b[x].x, acc2[y][x]);
                    acc2[y][x] = ffma2(a[y].y, b[x].y, acc2[y][x]);
                }
        }
    }

#pragma unroll
    for (int y = 0; y < 4; y++) {
#pragma unroll
        for (int x = 0; x < 4; x++) {
            int m = m0 + ty * 4 + y;
            int n = n0 + tx + 16 * x;
            float2 f = u2f(acc2[y][x]);
            float val = f.x + f.y + bias[n];
            if (permute) {
                int b_ = m >> 11;
                int s_ = m & 2047;
                int h_ = n >> 5;
                int d_ = n & 31;
                out[(((size_t)b_ * HH + h_) * SS + s_) * DK + d_] = val;
            } else {
                out[(size_t)m * NN + n] = val;
            }
        }
    }
}

// ---------------------------------------------------------------------------
// Tiled attention with distance-decay, log2-domain fixed-reference softmax.
// Block: 128 query rows of one (b,h). tx=tid&15 (cols c0=4tx..), ty=tid>>4
// (rows r0=8ty..). Scores kept as sc' = sc*log2(e).
// ---------------------------------------------------------------------------
struct AttnSmem {
    float Qs[32][132];    // [k][r]  query tile, transposed
    float Ks[32][68];     // [k][c]  key tile, transposed
    float Vst[32][68];    // [d][c]  value tile, transposed
    float ps[128][68];    // p2 tile
    float rowA[128][17];  // one-shot combine buffer
    float s1s[128];       // softmax-1 sums (unnormalized, log2-ref 0)
    float l2s[128];       // softmax-2 sums
};

template <bool MASK>
__device__ __forceinline__ void compute_scores(
    const AttnSmem* S, int r0, int c0, int i0, int j0,
    float scalep, float scr[8][4])
{
#pragma unroll
    for (int y = 0; y < 8; y++)
#pragma unroll
        for (int x = 0; x < 4; x++) scr[y][x] = 0.f;

#pragma unroll
    for (int k = 0; k < 32; k++) {
        float4 a0 = *(const float4*)&S->Qs[k][r0];
        float4 a1 = *(const float4*)&S->Qs[k][r0 + 4];
        float4 bb = *(const float4*)&S->Ks[k][c0];
        float a[8] = {a0.x, a0.y, a0.z, a0.w, a1.x, a1.y, a1.z, a1.w};
        float b[4] = {bb.x, bb.y, bb.z, bb.w};
#pragma unroll
        for (int y = 0; y < 8; y++)
#pragma unroll
            for (int x = 0; x < 4; x++) scr[y][x] += a[y] * b[x];
    }
#pragma unroll
    for (int y = 0; y < 8; y++) {
        int i = i0 + r0 + y;
#pragma unroll
        for (int x = 0; x < 4; x++) {
            scr[y][x] *= scalep;
            if (MASK && (j0 + c0 + x > i)) scr[y][x] = -1e30f;
        }
    }
}

__global__ __launch_bounds__(256, 2)
void attn_tile_kernel(const float* __restrict__ qh,
                      const float* __restrict__ kh,
                      const float* __restrict__ vh,
                      const float* __restrict__ gammas,
                      float* __restrict__ ao)
{
    extern __shared__ char smem_raw[];
    AttnSmem* S = (AttnSmem*)smem_raw;

    const int tid = threadIdx.x;
    const int tx = tid & 15;
    const int ty = tid >> 4;
    const int r0 = ty * 8;
    const int c0 = tx * 4;

    // heavy q-tiles launch first
    const int qt = (NQT - 1) - (blockIdx.x >> 5);
    const int bh = blockIdx.x & 31;
    const int h = bh & (HH - 1);
    const int b = bh >> 3;
    const int i0 = qt * QT;
    const int jtiles = 2 * qt + 2;

    const float* qbase = qh + (size_t)bh * SS * DK;
    const float* kbase = kh + (size_t)bh * SS * DK;
    const float* vbase = vh + (size_t)bh * SS * DK;

    const float LOG2E = 1.44269504088896340736f;
    const float g = gammas[h];
    const float gammap = -log1pf(__expf(g)) * LOG2E;      // exp(d*gamma)=ex2(d*gammap)
    const float scalep = 0.17677669529663687f * LOG2E;    // (1/sqrt(32))*log2(e)

    // ---- load Q tile (transposed) ----
#pragma unroll
    for (int l = 0; l < 4; l++) {
        int idx = tid + l * 256;
        int r = idx >> 3;
        int kq = (idx & 7) * 4;
        float4 qv = *(const float4*)(qbase + (size_t)(i0 + r) * DK + kq);
        S->Qs[kq + 0][r] = qv.x;
        S->Qs[kq + 1][r] = qv.y;
        S->Qs[kq + 2][r] = qv.z;
        S->Qs[kq + 3][r] = qv.w;
    }

    float rs1[8];
#pragma unroll
    for (int y = 0; y < 8; y++) rs1[y] = 0.f;

    float scr[8][4];

    // =================== PASS 1: softmax-1 sums (fixed ref 0) ==============
#define P1_BODY(MASKF)                                                         \
    {                                                                          \
        __syncthreads();                                                       \
        _Pragma("unroll")                                                      \
        for (int l = 0; l < 2; l++) {                                          \
            int idx = tid + l * 256;                                           \
            int c = idx >> 3;                                                  \
            int kq = (idx & 7) * 4;                                            \
            float4 kv = *(const float4*)(kbase + (size_t)(j0 + c) * DK + kq);  \
            S->Ks[kq + 0][c] = kv.x;                                           \
            S->Ks[kq + 1][c] = kv.y;                                           \
            S->Ks[kq + 2][c] = kv.z;                                           \
            S->Ks[kq + 3][c] = kv.w;                                           \
        }                                                                      \
        __syncthreads();                                                       \
        compute_scores<MASKF>(S, r0, c0, i0, j0, scalep, scr);                 \
        _Pragma("unroll")                                                      \
        for (int y = 0; y < 8; y++) {                                          \
            float e0 = ex2(scr[y][0]);                                         \
            float e1 = ex2(scr[y][1]);                                         \
            float e2 = ex2(scr[y][2]);                                         \
            float e3 = ex2(scr[y][3]);                                         \
            rs1[y] += (e0 + e1) + (e2 + e3);                                   \
        }                                                                      \
    }

    for (int jt = 0; jt < 2 * qt; jt++) {
        const int j0 = jt * JT;
        P1_BODY(false)
    }
    for (int jt = 2 * qt; jt < jtiles; jt++) {
        const int j0 = jt * JT;
        P1_BODY(true)
    }
#undef P1_BODY

    // ---- one-shot combine of the 16 sum partials per row ----
#pragma unroll
    for (int y = 0; y < 8; y++) S->rowA[r0 + y][tx] = rs1[y];
    __syncthreads();
    if (tid < QT) {
        int r = tid;
        float s = 0.f;
#pragma unroll
        for (int t = 0; t < 16; t++) s += S->rowA[r][t];
        S->s1s[r] = s;
    }
    __syncthreads();

    float Sv[8], ri1[8], rl2[8], rcarry[8];
    float acc[8][2];
#pragma unroll
    for (int y = 0; y < 8; y++) {
        Sv[y] = S->s1s[r0 + y];
        ri1[y] = 1.f / Sv[y];
        rl2[y] = 0.f;
        rcarry[y] = 0.f;
        acc[y][0] = 0.f;
        acc[y][1] = 0.f;
    }

    // =================== PASS 2: decay + softmax-2 + PV ====================
#define P2_BODY(MASKF)                                                         \
    {                                                                          \
        __syncthreads();                                                       \
        _Pragma("unroll")                                                      \
        for (int l = 0; l < 2; l++) {                                          \
            int idx = tid + l * 256;                                           \
            int c = idx >> 3;                                                  \
            int kq = (idx & 7) * 4;                                            \
            float4 kv = *(const float4*)(kbase + (size_t)(j0 + c) * DK + kq);  \
            S->Ks[kq + 0][c] = kv.x;                                           \
            S->Ks[kq + 1][c] = kv.y;                                           \
            S->Ks[kq + 2][c] = kv.z;                                           \
            S->Ks[kq + 3][c] = kv.w;                                           \
            float4 vv = *(const float4*)(vbase + (size_t)(j0 + c) * DK + kq);  \
            S->Vst[kq + 0][c] = vv.x;                                          \
            S->Vst[kq + 1][c] = vv.y;                                          \
            S->Vst[kq + 2][c] = vv.z;                                          \
            S->Vst[kq + 3][c] = vv.w;                                          \
        }                                                                      \
        __syncthreads();                                                       \
        compute_scores<MASKF>(S, r0, c0, i0, j0, scalep, scr);                 \
        _Pragma("unroll")                                                      \
        for (int y = 0; y < 8; y++) {                                          \
            const int i = i0 + r0 + y;                                         \
            /* raw exp2 s1 terms + in-thread inclusive prefix */               \
            float t0 = ex2(scr[y][0]);                                         \
            float t1 = ex2(scr[y][1]);                                         \
            float t2 = ex2(scr[y][2]);                                         \
            float t3 = ex2(scr[y][3]);                                         \
            float q1 = t0, q2 = q1 + t1, q3 = q2 + t2, q4 = q3 + t3;           \
            /* scan of 16 chunk totals within the half-warp segment */         \
            float incl = q4;                                                   \
            _Pragma("unroll")                                                  \
            for (int off = 1; off < 16; off <<= 1) {                           \
                float vsh = __shfl_up_sync(0xffffffffu, incl, off, 16);        \
                if (tx >= off) incl += vsh;                                    \
            }                                                                  \
            float base = rcarry[y] + (incl - q4);                              \
            rcarry[y] += __shfl_sync(0xffffffffu, incl, 15, 16);               \
            float cums[4] = {base + q1, base + q2, base + q3, base + q4};      \
            /* decay: dist^2 = (S-cumu)*(i-j)*is1 */                           \
            float fi = (float)(i - j0 - c0);                                   \
            float is1 = ri1[y];                                                \
            float fis = fi * is1;                                              \
            float p[4];                                                        \
            _Pragma("unroll")                                                  \
            for (int x = 0; x < 4; x++) {                                      \
                float rem = Sv[y] - cums[x];                                   \
                float posn = __fmaf_rn(-(float)x, is1, fis);                   \
                float d2 = fmaxf(rem * posn, 0.f);                             \
                float dist = sqrt_approx(d2);                                  \
                float eff = fmaxf(ex2(dist * gammap), 1e-5f);                  \
                p[x] = ex2(scr[y][x] * eff);                                   \
            }                                                                  \
            rl2[y] += (p[0] + p[1]) + (p[2] + p[3]);                           \
            *(float4*)&S->ps[r0 + y][c0] = make_float4(p[0], p[1], p[2], p[3]);\
        }                                                                      \
        __syncwarp();                                                          \
        /* PV: out[r][d] += sum_c p[r][c] * V[c][d], d = tx and tx+16 */       \
        _Pragma("unroll 4")                                                    \
        for (int cb = 0; cb < 16; cb++) {                                      \
            float4 v0 = *(const float4*)&S->Vst[tx][cb * 4];                   \
            float4 v1 = *(const float4*)&S->Vst[tx + 16][cb * 4];              \
            _Pragma("unroll")                                                  \
            for (int y = 0; y < 8; y++) {                                      \
                float4 pp = *(const float4*)&S->ps[r0 + y][cb * 4];            \
                acc[y][0] += pp.x * v0.x + pp.y * v0.y + pp.z * v0.z +         \
                             pp.w * v0.w;                                      \
                acc[y][1] += pp.x * v1.x + pp.y * v1.y + pp.z * v1.z +         \
                             pp.w * v1.w;                                      \
            }                                                                  \
        }                                                                      \
    }

    for (int jt = 0; jt < 2 * qt; jt++) {
        const int j0 = jt * JT;
        P2_BODY(false)
    }
    for (int jt = 2 * qt; jt < jtiles; jt++) {
        const int j0 = jt * JT;
        P2_BODY(true)
    }
#undef P2_BODY

    // ---- combine l2 partials once, then write output ----
    __syncthreads();
#pragma unroll
    for (int y = 0; y < 8; y++) S->rowA[r0 + y][tx] = rl2[y];
    __syncthreads();
    if (tid < QT) {
        int r = tid;
        float s = 0.f;
#pragma unroll
        for (int t = 0; t < 16; t++) s += S->rowA[r][t];
        S->l2s[r] = s;
    }
    __syncthreads();

#pragma unroll
    for (int y = 0; y < 8; y++) {
        int i = i0 + r0 + y;
        float inv = 1.f / S->l2s[r0 + y];
        size_t base = ((size_t)b * SS + i) * EE + h * DK;
        ao[base + tx] = acc[y][0] * inv;
        ao[base + tx + 16] = acc[y][1] * inv;
    }
}

// ---------------------------------------------------------------------------
extern "C" void kernel_launch(void* const* d_in, const int* in_sizes, int n_in,
                              void* d_out, int out_size)
{
    const float* q      = (const float*)d_in[0];
    const float* k      = (const float*)d_in[1];
    const float* v      = (const float*)d_in[2];
    // d_in[3] = mask (unused; causal structure known)
    const float* Wq     = (const float*)d_in[4];
    const float* bq     = (const float*)d_in[5];
    const float* Wk     = (const float*)d_in[6];
    const float* bk     = (const float*)d_in[7];
    const float* Wv     = (const float*)d_in[8];
    const float* bv     = (const float*)d_in[9];
    const float* Wo     = (const float*)d_in[10];
    const float* bo     = (const float*)d_in[11];
    const float* gammas = (const float*)d_in[12];
    float* out = (float*)d_out;

    float *qh, *kh, *vh, *ao;
    cudaGetSymbolAddress((void**)&qh, g_qh);
    cudaGetSymbolAddress((void**)&kh, g_kh);
    cudaGetSymbolAddress((void**)&vh, g_vh);
    cudaGetSymbolAddress((void**)&ao, g_ao);

    static bool attr_set = false;
    if (!attr_set) {
        cudaFuncSetAttribute(attn_tile_kernel,
                             cudaFuncAttributeMaxDynamicSharedMemorySize,
                             (int)sizeof(AttnSmem));
        attr_set = true;
    }

    dim3 gblk(256);
    dim3 ggrid(MM / 64, NN / 64);

    gemm_bias_kernel<<<ggrid, gblk>>>(q, Wq, bq, qh, 1);
    gemm_bias_kernel<<<ggrid, gblk>>>(k, Wk, bk, kh, 1);
    gemm_bias_kernel<<<ggrid, gblk>>>(v, Wv, bv, vh, 1);

    attn_tile_kernel<<<BB * HH * NQT, 256, sizeof(AttnSmem)>>>(qh, kh, vh, gammas, ao);

    gemm_bias_kernel<<<ggrid, gblk>>>(ao, Wo, bo, out, 0);
}